// round 2
// baseline (speedup 1.0000x reference)
#include <cuda_runtime.h>
#include <cstdint>

// RecurrentGCN (DCRNN GRU step, K=1) on GB300.
// inputs: 0:x[N,10] 1:edge_index(unused) 2:edge_weight(unused) 3:h[N,32]
//         4:W_z[2,42,32] 5:b_z[32] 6:W_r 7:b_r 8:W_h 9:b_h 10:W_lin[2,32] 11:b_lin[2]
// output: concat( out[N,2], h_new[N,32] )  (float32)

#define F_IN 10
#define HID 32
#define DIN 42          // F_IN + HID
#define THREADS 128

// packed weight buffer layout (floats):
//   [0    .. 1344)  Wz = W_z[0]+W_z[1]  (42 x 32, row k major)
//   [1344 .. 2688)  Wr
//   [2688 .. 4032)  Wh
//   [4032 .. 4064)  b_z
//   [4064 .. 4096)  b_r
//   [4096 .. 4128)  b_h
//   [4128 .. 4192)  W_lin (2 x 32)
//   [4192 .. 4194)  b_lin
#define WBUF_FLOATS 4224
__device__ float g_wbuf[WBUF_FLOATS];

__global__ void prep_weights(const float* __restrict__ Wz, const float* __restrict__ Wr,
                             const float* __restrict__ Wh,
                             const float* __restrict__ bz, const float* __restrict__ br,
                             const float* __restrict__ bh,
                             const float* __restrict__ Wlin, const float* __restrict__ blin)
{
    int t = blockIdx.x * blockDim.x + threadIdx.x;
    const int G = DIN * HID;  // 1344
    if (t < G) {
        g_wbuf[t]          = Wz[t] + Wz[G + t];
        g_wbuf[G + t]      = Wr[t] + Wr[G + t];
        g_wbuf[2 * G + t]  = Wh[t] + Wh[G + t];
    }
    if (t < HID) {
        g_wbuf[4032 + t] = bz[t];
        g_wbuf[4064 + t] = br[t];
        g_wbuf[4096 + t] = bh[t];
    }
    if (t < 64) g_wbuf[4128 + t] = Wlin[t];
    if (t < 2)  g_wbuf[4192 + t] = blin[t];
}

// ---- packed f32x2 helpers (ptxas will not auto-fuse; must use PTX f32x2) ----
__device__ __forceinline__ unsigned long long pack2(float lo, float hi) {
    unsigned long long r;
    asm("mov.b64 %0, {%1, %2};" : "=l"(r) : "f"(lo), "f"(hi));
    return r;
}
__device__ __forceinline__ void unpack2(unsigned long long v, float& lo, float& hi) {
    asm("mov.b64 {%0, %1}, %2;" : "=f"(lo), "=f"(hi) : "l"(v));
}
__device__ __forceinline__ void fma2(unsigned long long& d, unsigned long long a, unsigned long long b) {
    asm("fma.rn.f32x2 %0, %1, %2, %0;" : "+l"(d) : "l"(a), "l"(b));
}
// ---- fast activations (MUFU) ----
__device__ __forceinline__ float ex2f(float x) { float y; asm("ex2.approx.f32 %0, %1;" : "=f"(y) : "f"(x)); return y; }
__device__ __forceinline__ float rcpf(float x) { float y; asm("rcp.approx.f32 %0, %1;" : "=f"(y) : "f"(x)); return y; }
__device__ __forceinline__ float sigm(float x) {
    // 1/(1+exp(-x)) = 1/(1+2^(-x*log2e))
    return rcpf(1.0f + ex2f(-1.4426950408889634f * x));
}
__device__ __forceinline__ float tanh_fast(float x) {
    // tanh(x) = 2*sigmoid(2x) - 1
    return fmaf(2.0f, sigm(2.0f * x), -1.0f);
}

__global__ __launch_bounds__(THREADS)
void dcrnn_kernel(const float* __restrict__ x, const float* __restrict__ h,
                  float* __restrict__ out, int n)
{
    __shared__ __align__(16) float sw[WBUF_FLOATS];
    for (int i = threadIdx.x; i < WBUF_FLOATS; i += THREADS) sw[i] = g_wbuf[i];
    __syncthreads();

    int i = blockIdx.x * THREADS + threadIdx.x;
    if (i >= n) return;

    // ---- load node inputs ----
    float xv[F_IN];
    {
        const float2* xp = reinterpret_cast<const float2*>(x + (size_t)i * F_IN);
        #pragma unroll
        for (int k = 0; k < F_IN / 2; k++) { float2 v = xp[k]; xv[2*k] = v.x; xv[2*k+1] = v.y; }
    }
    float hv[HID];
    {
        const float4* hp = reinterpret_cast<const float4*>(h + (size_t)i * HID);
        #pragma unroll
        for (int k = 0; k < HID / 4; k++) {
            float4 v = hp[k];
            hv[4*k] = v.x; hv[4*k+1] = v.y; hv[4*k+2] = v.z; hv[4*k+3] = v.w;
        }
    }

    // ---- phase 1: z and r gate pre-activations (packed f32x2 accumulators) ----
    unsigned long long az[16], ar[16];
    {
        const unsigned long long* bz = reinterpret_cast<const unsigned long long*>(sw + 4032);
        const unsigned long long* br = reinterpret_cast<const unsigned long long*>(sw + 4064);
        #pragma unroll
        for (int j = 0; j < 16; j++) { az[j] = bz[j]; ar[j] = br[j]; }
    }
    #pragma unroll
    for (int k = 0; k < DIN; k++) {
        float a = (k < F_IN) ? xv[k] : hv[k - F_IN];
        unsigned long long a2 = pack2(a, a);
        const ulonglong2* wz = reinterpret_cast<const ulonglong2*>(sw + k * HID);
        const ulonglong2* wr = reinterpret_cast<const ulonglong2*>(sw + 1344 + k * HID);
        #pragma unroll
        for (int jp = 0; jp < 8; jp++) {
            ulonglong2 wa = wz[jp];
            ulonglong2 wb = wr[jp];
            fma2(az[2*jp],   a2, wa.x);
            fma2(az[2*jp+1], a2, wa.y);
            fma2(ar[2*jp],   a2, wb.x);
            fma2(ar[2*jp+1], a2, wb.y);
        }
    }

    // ---- activations: z = sigmoid, rh = sigmoid(r)*h ----
    float zv[HID], rh[HID];
    #pragma unroll
    for (int jp = 0; jp < 16; jp++) {
        float a, b;
        unpack2(az[jp], a, b);
        zv[2*jp]   = sigm(a);
        zv[2*jp+1] = sigm(b);
        unpack2(ar[jp], a, b);
        rh[2*jp]   = sigm(a) * hv[2*jp];
        rh[2*jp+1] = sigm(b) * hv[2*jp+1];
    }

    // ---- phase 2: h_tilde pre-activation over cat([x, r*h]) ----
    unsigned long long ah[16];
    {
        const unsigned long long* bh = reinterpret_cast<const unsigned long long*>(sw + 4096);
        #pragma unroll
        for (int j = 0; j < 16; j++) ah[j] = bh[j];
    }
    #pragma unroll
    for (int k = 0; k < DIN; k++) {
        float a = (k < F_IN) ? xv[k] : rh[k - F_IN];
        unsigned long long a2 = pack2(a, a);
        const ulonglong2* wh = reinterpret_cast<const ulonglong2*>(sw + 2688 + k * HID);
        #pragma unroll
        for (int jp = 0; jp < 8; jp++) {
            ulonglong2 w = wh[jp];
            fma2(ah[2*jp],   a2, w.x);
            fma2(ah[2*jp+1], a2, w.y);
        }
    }

    // ---- GRU blend + ReLU-linear head ----
    float hn[HID];
    #pragma unroll
    for (int jp = 0; jp < 16; jp++) {
        float a, b;
        unpack2(ah[jp], a, b);
        float t0 = tanh_fast(a);
        float t1 = tanh_fast(b);
        // h_new = z*h + (1-z)*t = t + z*(h - t)
        hn[2*jp]   = fmaf(zv[2*jp],   hv[2*jp]   - t0, t0);
        hn[2*jp+1] = fmaf(zv[2*jp+1], hv[2*jp+1] - t1, t1);
    }

    float o0 = sw[4192], o1 = sw[4193];
    #pragma unroll
    for (int j = 0; j < HID; j++) {
        float rel = fmaxf(hn[j], 0.0f);
        o0 = fmaf(rel, sw[4128 + j], o0);
        o1 = fmaf(rel, sw[4160 + j], o1);
    }

    // ---- stores: out[N,2] then h_new[N,32] ----
    reinterpret_cast<float2*>(out)[i] = make_float2(o0, o1);
    float4* hop = reinterpret_cast<float4*>(out + (size_t)2 * n + (size_t)i * HID);
    #pragma unroll
    for (int k = 0; k < HID / 4; k++)
        hop[k] = make_float4(hn[4*k], hn[4*k+1], hn[4*k+2], hn[4*k+3]);
}

extern "C" void kernel_launch(void* const* d_in, const int* in_sizes, int n_in,
                              void* d_out, int out_size)
{
    const float* x     = (const float*)d_in[0];
    // d_in[1] edge_index (int64), d_in[2] edge_weight: unused (K=1 collapses DConv)
    const float* h     = (const float*)d_in[3];
    const float* Wz    = (const float*)d_in[4];
    const float* bz    = (const float*)d_in[5];
    const float* Wr    = (const float*)d_in[6];
    const float* br    = (const float*)d_in[7];
    const float* Wh    = (const float*)d_in[8];
    const float* bh    = (const float*)d_in[9];
    const float* Wlin  = (const float*)d_in[10];
    const float* blin  = (const float*)d_in[11];
    float* out = (float*)d_out;

    int n = in_sizes[0] / F_IN;

    prep_weights<<<6, 256>>>(Wz, Wr, Wh, bz, br, bh, Wlin, blin);
    int blocks = (n + THREADS - 1) / THREADS;
    dcrnn_kernel<<<blocks, THREADS>>>(x, h, out, n);
}

// round 5
// speedup vs baseline: 1.3060x; 1.3060x over previous
#include <cuda_runtime.h>
#include <cstdint>

// RecurrentGCN (DCRNN GRU step, K=1) on GB300 — Round 4: constant-memory weights,
// with the symbol-address plumbing FIXED (R3 passed a __device__ symbol's host
// shadow as a device src pointer; the copy silently failed -> zero weights).
//
// inputs: 0:x[N,10] 1:edge_index(unused) 2:edge_weight(unused) 3:h[N,32]
//         4:W_z[2,42,32] 5:b_z[32] 6:W_r 7:b_r 8:W_h 9:b_h 10:W_lin[2,32] 11:b_lin[2]
// output: concat( out[N,2], h_new[N,32] )  (float32)

#define F_IN 10
#define HID 32
#define DIN 42          // F_IN + HID
#define THREADS 128

// packed weight buffer layout (floats):
//   [0    .. 1344)  Wz = W_z[0]+W_z[1]  (42 x 32, row k major)
//   [1344 .. 2688)  Wr
//   [2688 .. 4032)  Wh
//   [4032 .. 4064)  b_z
//   [4064 .. 4096)  b_r
//   [4096 .. 4128)  b_h
//   [4128 .. 4192)  W_lin (2 x 32)
//   [4192 .. 4194)  b_lin
#define WBUF_FLOATS 4224
__device__    float g_wstage[WBUF_FLOATS];   // staging (written by prep kernel)
__constant__  float c_wbuf[WBUF_FLOATS];     // hot copy (uniform/constant port)

__global__ void prep_weights(const float* __restrict__ Wz, const float* __restrict__ Wr,
                             const float* __restrict__ Wh,
                             const float* __restrict__ bz, const float* __restrict__ br,
                             const float* __restrict__ bh,
                             const float* __restrict__ Wlin, const float* __restrict__ blin)
{
    int t = blockIdx.x * blockDim.x + threadIdx.x;
    const int G = DIN * HID;  // 1344
    if (t < G) {
        g_wstage[t]         = Wz[t] + Wz[G + t];
        g_wstage[G + t]     = Wr[t] + Wr[G + t];
        g_wstage[2 * G + t] = Wh[t] + Wh[G + t];
    }
    if (t < HID) {
        g_wstage[4032 + t] = bz[t];
        g_wstage[4064 + t] = br[t];
        g_wstage[4096 + t] = bh[t];
    }
    if (t < 64) g_wstage[4128 + t] = Wlin[t];
    if (t < 2)  g_wstage[4192 + t] = blin[t];
}

// ---- packed f32x2 helpers (only expressible via PTX; ptxas won't auto-fuse) ----
__device__ __forceinline__ unsigned long long pack2(float lo, float hi) {
    unsigned long long r;
    asm("mov.b64 %0, {%1, %2};" : "=l"(r) : "f"(lo), "f"(hi));
    return r;
}
__device__ __forceinline__ void unpack2(unsigned long long v, float& lo, float& hi) {
    asm("mov.b64 {%0, %1}, %2;" : "=f"(lo), "=f"(hi) : "l"(v));
}
__device__ __forceinline__ void fma2(unsigned long long& d, unsigned long long a, unsigned long long b) {
    asm("fma.rn.f32x2 %0, %1, %2, %0;" : "+l"(d) : "l"(a), "l"(b));
}
// ---- fast activations (MUFU) ----
__device__ __forceinline__ float ex2f(float x) { float y; asm("ex2.approx.f32 %0, %1;" : "=f"(y) : "f"(x)); return y; }
__device__ __forceinline__ float rcpf(float x) { float y; asm("rcp.approx.f32 %0, %1;" : "=f"(y) : "f"(x)); return y; }
__device__ __forceinline__ float sigm(float x) {
    return rcpf(1.0f + ex2f(-1.4426950408889634f * x));   // 1/(1+2^(-x*log2e))
}
__device__ __forceinline__ float tanh_fast(float x) {
    return fmaf(2.0f, sigm(2.0f * x), -1.0f);             // 2*sigmoid(2x)-1
}

// constant-memory 64-bit view; after full unroll every index is a literal ->
// const-bank offset -> uniform/constant-port load, zero L1tex traffic.
__device__ __forceinline__ unsigned long long cw64(int idx_f) {
    return reinterpret_cast<const unsigned long long*>(c_wbuf)[idx_f >> 1];
}

__global__ __launch_bounds__(THREADS)
void dcrnn_kernel(const float* __restrict__ x, const float* __restrict__ h,
                  float* __restrict__ out, int n)
{
    int i = blockIdx.x * THREADS + threadIdx.x;
    if (i >= n) return;

    // ---- load node inputs (coalesced LDG) ----
    float xv[F_IN];
    {
        const float2* xp = reinterpret_cast<const float2*>(x + (size_t)i * F_IN);
        #pragma unroll
        for (int k = 0; k < F_IN / 2; k++) { float2 v = xp[k]; xv[2*k] = v.x; xv[2*k+1] = v.y; }
    }
    float hv[HID];
    {
        const float4* hp = reinterpret_cast<const float4*>(h + (size_t)i * HID);
        #pragma unroll
        for (int k = 0; k < HID / 4; k++) {
            float4 v = hp[k];
            hv[4*k] = v.x; hv[4*k+1] = v.y; hv[4*k+2] = v.z; hv[4*k+3] = v.w;
        }
    }

    // ---- phase 1: z and r gate pre-activations (packed f32x2 accumulators) ----
    unsigned long long az[16], ar[16];
    #pragma unroll
    for (int j = 0; j < 16; j++) { az[j] = cw64(4032 + 2*j); ar[j] = cw64(4064 + 2*j); }

    #pragma unroll
    for (int k = 0; k < DIN; k++) {
        float a = (k < F_IN) ? xv[k] : hv[k - F_IN];
        unsigned long long a2 = pack2(a, a);
        #pragma unroll
        for (int jp = 0; jp < 16; jp++) {
            fma2(az[jp], a2, cw64(k * HID + 2*jp));            // Wz
            fma2(ar[jp], a2, cw64(1344 + k * HID + 2*jp));     // Wr
        }
    }

    // ---- activations: z = sigmoid, rh = sigmoid(r)*h ----
    float zv[HID], rh[HID];
    #pragma unroll
    for (int jp = 0; jp < 16; jp++) {
        float a, b;
        unpack2(az[jp], a, b);
        zv[2*jp]   = sigm(a);
        zv[2*jp+1] = sigm(b);
        unpack2(ar[jp], a, b);
        rh[2*jp]   = sigm(a) * hv[2*jp];
        rh[2*jp+1] = sigm(b) * hv[2*jp+1];
    }

    // ---- phase 2: h_tilde pre-activation over cat([x, r*h]) ----
    unsigned long long ah[16];
    #pragma unroll
    for (int j = 0; j < 16; j++) ah[j] = cw64(4096 + 2*j);

    #pragma unroll
    for (int k = 0; k < DIN; k++) {
        float a = (k < F_IN) ? xv[k] : rh[k - F_IN];
        unsigned long long a2 = pack2(a, a);
        #pragma unroll
        for (int jp = 0; jp < 16; jp++)
            fma2(ah[jp], a2, cw64(2688 + k * HID + 2*jp));     // Wh
    }

    // ---- GRU blend + ReLU-linear head ----
    float hn[HID];
    #pragma unroll
    for (int jp = 0; jp < 16; jp++) {
        float a, b;
        unpack2(ah[jp], a, b);
        float t0 = tanh_fast(a);
        float t1 = tanh_fast(b);
        // h_new = z*h + (1-z)*t = t + z*(h - t)
        hn[2*jp]   = fmaf(zv[2*jp],   hv[2*jp]   - t0, t0);
        hn[2*jp+1] = fmaf(zv[2*jp+1], hv[2*jp+1] - t1, t1);
    }

    float o0 = c_wbuf[4192], o1 = c_wbuf[4193];
    #pragma unroll
    for (int j = 0; j < HID; j++) {
        float rel = fmaxf(hn[j], 0.0f);
        o0 = fmaf(rel, c_wbuf[4128 + j], o0);
        o1 = fmaf(rel, c_wbuf[4160 + j], o1);
    }

    // ---- stores: out[N,2] then h_new[N,32] ----
    reinterpret_cast<float2*>(out)[i] = make_float2(o0, o1);
    float4* hop = reinterpret_cast<float4*>(out + (size_t)2 * n + (size_t)i * HID);
    #pragma unroll
    for (int k = 0; k < HID / 4; k++)
        hop[k] = make_float4(hn[4*k], hn[4*k+1], hn[4*k+2], hn[4*k+3]);
}

extern "C" void kernel_launch(void* const* d_in, const int* in_sizes, int n_in,
                              void* d_out, int out_size)
{
    const float* x     = (const float*)d_in[0];
    // d_in[1] edge_index (int64), d_in[2] edge_weight: unused (K=1 collapses DConv)
    const float* h     = (const float*)d_in[3];
    const float* Wz    = (const float*)d_in[4];
    const float* bz    = (const float*)d_in[5];
    const float* Wr    = (const float*)d_in[6];
    const float* br    = (const float*)d_in[7];
    const float* Wh    = (const float*)d_in[8];
    const float* bh    = (const float*)d_in[9];
    const float* Wlin  = (const float*)d_in[10];
    const float* blin  = (const float*)d_in[11];
    float* out = (float*)d_out;

    int n = in_sizes[0] / F_IN;

    // Resolve REAL device addresses of the module symbols (non-stream API,
    // safe during graph capture). This is the fix for R3: passing the
    // __device__ symbol itself gives the host shadow, not a device pointer.
    void* g_addr = nullptr;
    void* c_addr = nullptr;
    cudaGetSymbolAddress(&g_addr, g_wstage);
    cudaGetSymbolAddress(&c_addr, c_wbuf);

    prep_weights<<<6, 256>>>(Wz, Wr, Wh, bz, br, bh, Wlin, blin);
    // plain D2D async copy into the constant bank (graph-capturable, no alloc)
    cudaMemcpyAsync(c_addr, g_addr, WBUF_FLOATS * sizeof(float),
                    cudaMemcpyDeviceToDevice, 0);
    int blocks = (n + THREADS - 1) / THREADS;
    dcrnn_kernel<<<blocks, THREADS>>>(x, h, out, n);
}